// round 17
// baseline (speedup 1.0000x reference)
#include <cuda_runtime.h>
#include <cuda_bf16.h>
#include <cuda_fp16.h>
#include <cstdint>
#include <math.h>

// Problem constants
constexpr int NN   = 20000;
constexpr int EE   = 320000;
constexpr int FF   = 256;
constexpr int HH   = 8;
constexpr int DD   = 64;
constexpr int HD   = 512;
constexpr int MM   = 2;
constexpr int CC   = 5;
constexpr int HIDN = 128;
constexpr int NB   = 80;
constexpr int NPAD = 20096;   // 157 * 128

// ---------------- device scratch ----------------
__device__ __half g_feat_h[MM][NN][HD];
__device__ __half g_z_h[MM][NN][HD];
__device__ float g_el[MM][NN][HH];
__device__ float g_er[MM][NN][HH];
__device__ int   g_deg[MM][NN];
__device__ int   g_rowptr[MM][NN + 1];
__device__ int   g_cur[MM][NN];
__device__ int   g_csr_src[MM][EE];
__device__ float g_wsum[MM];
__device__ float g_beta[MM];
__device__ int   g_psum[MM][NB];
__device__ int   g_boff[MM][NB];
__device__ __half g_h_h[NPAD][FF];           // h, fp16
__device__ __half g_Wt_h[MM][HD][FF];        // W transposed [n][k], fp16
__device__ __half g_W1t_h[HIDN][HD];         // sem_W1 transposed [n][k], fp16

// ---------------- helpers ----------------
__device__ __forceinline__ float fast_tanh(float x) {
    float e2 = __expf(2.f * x);
    return __fdividef(e2 - 1.f, e2 + 1.f);
}
__device__ __forceinline__ uint32_t comb2(uint32_t a, uint32_t b, float b0, float b1) {
    float2 fa = __half22float2(*(__half2*)&a);
    float2 fb = __half22float2(*(__half2*)&b);
    __half2 r = __floats2half2_rn(b0 * fa.x + b1 * fb.x, b0 * fa.y + b1 * fb.y);
    return *(uint32_t*)&r;
}
#define MMA_F16(d, a, b) \
    asm volatile( \
        "mma.sync.aligned.m16n8k16.row.col.f32.f16.f16.f32 " \
        "{%0,%1,%2,%3}, {%4,%5,%6,%7}, {%8,%9}, {%0,%1,%2,%3};" \
        : "+f"((d)[0]), "+f"((d)[1]), "+f"((d)[2]), "+f"((d)[3]) \
        : "r"((a)[0]), "r"((a)[1]), "r"((a)[2]), "r"((a)[3]), \
          "r"((b)[0]), "r"((b)[1]))
#define LDSM_X4(r, addr) \
    asm volatile("ldmatrix.sync.aligned.m8n8.x4.shared.b16 {%0,%1,%2,%3}, [%4];" \
        : "=r"((r)[0]), "=r"((r)[1]), "=r"((r)[2]), "=r"((r)[3]) : "r"(addr))
#define CP_ASYNC16(smem_u32, gptr) \
    asm volatile("cp.async.cg.shared.global [%0], [%1], 16;" \
        :: "r"(smem_u32), "l"(gptr) : "memory")
#define CP_COMMIT() asm volatile("cp.async.commit_group;" ::: "memory")
#define CP_WAIT(n)  asm volatile("cp.async.wait_group %0;" :: "n"(n) : "memory")
#define SMEM_U32(v, p) \
    asm("{ .reg .u64 t; cvta.to.shared.u64 t, %1; cvt.u32.u64 %0, t; }" : "=r"(v) : "l"(p))

// ---------------- conversion kernels ----------------
__global__ void conv_h_kernel(const float* __restrict__ h) {
    int idx = blockIdx.x * blockDim.x + threadIdx.x;   // one per 8 elements
    if (idx >= NPAD * FF / 8) return;
    int row = idx >> 5;
    int kk  = (idx & 31) * 8;
    uint4 hi = make_uint4(0, 0, 0, 0);
    if (row < NN) {
        const float* hp = &h[row * FF + kk];
        float4 a = *(const float4*)hp;
        float4 b = *(const float4*)(hp + 4);
        __half2 h0 = __floats2half2_rn(a.x, a.y);
        __half2 h1 = __floats2half2_rn(a.z, a.w);
        __half2 h2 = __floats2half2_rn(b.x, b.y);
        __half2 h3 = __floats2half2_rn(b.z, b.w);
        hi.x = *(uint32_t*)&h0; hi.y = *(uint32_t*)&h1;
        hi.z = *(uint32_t*)&h2; hi.w = *(uint32_t*)&h3;
    }
    *(uint4*)&g_h_h[row][kk] = hi;
}

__global__ void conv_w_kernel(const float* __restrict__ W) {
    __shared__ float tile[32][33];
    int mp = blockIdx.z;
    int n0 = blockIdx.x * 32, k0 = blockIdx.y * 32;
    int tx = threadIdx.x, ty = threadIdx.y;  // 32 x 8
#pragma unroll
    for (int j = 0; j < 4; j++)
        tile[ty + j * 8][tx] = W[mp * FF * HD + (k0 + ty + j * 8) * HD + n0 + tx];
    __syncthreads();
#pragma unroll
    for (int j = 0; j < 4; j++) {
        int n = n0 + ty + j * 8, k = k0 + tx;
        g_Wt_h[mp][n][k] = __float2half_rn(tile[tx][ty + j * 8]);
    }
}

__global__ void conv_w1t_kernel(const float* __restrict__ W1) {
    __shared__ float tile[32][33];
    int n0 = blockIdx.x * 32, k0 = blockIdx.y * 32;
    int tx = threadIdx.x, ty = threadIdx.y;
#pragma unroll
    for (int j = 0; j < 4; j++)
        tile[ty + j * 8][tx] = W1[(k0 + ty + j * 8) * HIDN + n0 + tx];
    __syncthreads();
#pragma unroll
    for (int j = 0; j < 4; j++) {
        int n = n0 + ty + j * 8, k = k0 + tx;
        g_W1t_h[n][k] = __float2half_rn(tile[tx][ty + j * 8]);
    }
}

// ---------------- feat GEMM: 128x128 block, fp16 single product, 2 stages ---
constexpr int STAGE_STRIDE = 20480;
constexpr int FEAT_SMEM_BYTES = 2 * STAGE_STRIDE + 1024;

__global__ void __launch_bounds__(256, 2)
feat_mma_kernel(const float* __restrict__ al, const float* __restrict__ ar,
                int mp) {
    extern __shared__ char smem[];
    float* s_al = (float*)(smem + 2 * STAGE_STRIDE);
    float* s_ar = s_al + 128;
    uint32_t smem_u32;
    SMEM_U32(smem_u32, smem);

    const int t = threadIdx.x, lane = t & 31, wid = t >> 5;
    const int wm = wid & 3, wn = wid >> 2;        // 4(m) x 2(n)
    const int rowBase = blockIdx.x * 128;
    const int colBase = blockIdx.y * 128;          // 2 heads

    if (t < 128) {
        s_al[t] = al[mp * HD + colBase + t];
        s_ar[t] = ar[mp * HD + colBase + t];
    }

    const int l_in  = lane & 7;
    const int l_t01 = (lane >> 3) & 1;
    const int l_t23 = lane >> 4;
    const uint32_t a_off0 = (uint32_t)(wm * 32 + l_in + l_t01 * 8) * 80 + l_t23 * 16;
    const uint32_t b_off0 = 10240u + (uint32_t)(wn * 64 + l_in + (lane >> 4) * 8) * 80
                          + ((lane >> 3) & 1) * 16;

    const int st_row = t >> 1;
    const int st_q0  = (t & 1) * 2;

    auto cp_stage = [&](int kc, int buf) {
        uint32_t base = smem_u32 + buf * STAGE_STRIDE;
        const int karow = rowBase + st_row;
        const int kbrow = colBase + st_row;
#pragma unroll
        for (int q = 0; q < 2; q++) {
            uint32_t so = (uint32_t)st_row * 80 + (st_q0 + q) * 16;
            int gk = kc * 32 + (st_q0 + q) * 8;
            CP_ASYNC16(base + so,          &g_h_h[karow][gk]);
            CP_ASYNC16(base + 10240 + so,  &g_Wt_h[mp][kbrow][gk]);
        }
    };

    float d[2][8][4] = {};

    cp_stage(0, 0);
    CP_COMMIT();

    for (int kc = 0; kc < 8; kc++) {
        const int cur = kc & 1;
        if (kc < 7) {
            cp_stage(kc + 1, cur ^ 1);
            CP_COMMIT();
            CP_WAIT(1);
        } else {
            CP_WAIT(0);
        }
        __syncthreads();

        const uint32_t bufb = smem_u32 + cur * STAGE_STRIDE;

#pragma unroll
        for (int ks = 0; ks < 2; ks++) {
            const uint32_t kb = (uint32_t)ks * 32;
            uint32_t ah[2][4], bh_r[4][4];
#pragma unroll
            for (int mi = 0; mi < 2; mi++)
                LDSM_X4(ah[mi], bufb + a_off0 + (uint32_t)(mi * 16) * 80 + kb);
#pragma unroll
            for (int p = 0; p < 4; p++)
                LDSM_X4(bh_r[p], bufb + b_off0 + (uint32_t)(p * 16) * 80 + kb);
#pragma unroll
            for (int mi = 0; mi < 2; mi++)
#pragma unroll
                for (int p = 0; p < 4; p++) {
#pragma unroll
                    for (int q = 0; q < 2; q++) {
                        int ni = p * 2 + q;
                        uint32_t bhq[2] = { bh_r[p][q * 2], bh_r[p][q * 2 + 1] };
                        MMA_F16(d[mi][ni], ah[mi], bhq);
                    }
                }
        }
        __syncthreads();
    }

    // ---- epilogue ----
    const int head = colBase / DD + wn;
#pragma unroll
    for (int mi = 0; mi < 2; mi++) {
#pragma unroll
        for (int half = 0; half < 2; half++) {
            int r = wm * 32 + mi * 16 + half * 8 + (lane >> 2);
            int grow = rowBase + r;
            float el = 0.f, er = 0.f;
#pragma unroll
            for (int ni = 0; ni < 8; ni++) {
                float v0 = d[mi][ni][half * 2 + 0];
                float v1 = d[mi][ni][half * 2 + 1];
                int c = wn * 64 + ni * 8 + (lane & 3) * 2;
                el += v0 * s_al[c] + v1 * s_al[c + 1];
                er += v0 * s_ar[c] + v1 * s_ar[c + 1];
                if (grow < NN) {
                    __half2 hv = __floats2half2_rn(v0, v1);
                    *(__half2*)&g_feat_h[mp][grow][colBase + c] = hv;
                }
            }
            el += __shfl_xor_sync(0xffffffffu, el, 1);
            el += __shfl_xor_sync(0xffffffffu, el, 2);
            er += __shfl_xor_sync(0xffffffffu, er, 1);
            er += __shfl_xor_sync(0xffffffffu, er, 2);
            if ((lane & 3) == 0 && grow < NN) {
                g_el[mp][grow][head] = el;
                g_er[mp][grow][head] = er;
            }
        }
    }
}

// ---------------- CSR build (per metapath) ----------------
__global__ void count_kernel(const int* __restrict__ dst, int mp) {
    int e = blockIdx.x * blockDim.x + threadIdx.x;
    if (e < EE) atomicAdd(&g_deg[mp][dst[mp * EE + e]], 1);
}

__global__ void scan_partial(int mp) {
    int i = blockIdx.x * 256 + threadIdx.x;
    int v = (i < NN) ? g_deg[mp][i] : 0;
#pragma unroll
    for (int off = 16; off; off >>= 1) v += __shfl_xor_sync(0xffffffffu, v, off);
    __shared__ int ws[8];
    if ((threadIdx.x & 31) == 0) ws[threadIdx.x >> 5] = v;
    __syncthreads();
    if (threadIdx.x == 0) {
        int s = 0;
#pragma unroll
        for (int w = 0; w < 8; w++) s += ws[w];
        g_psum[mp][blockIdx.x] = s;
    }
}

__global__ void scan_mid(int mp) {
    int t = threadIdx.x, lane = t & 31, wid = t >> 5;
    int v = (t < NB) ? g_psum[mp][t] : 0;
    int x = v;
#pragma unroll
    for (int off = 1; off < 32; off <<= 1) {
        int y = __shfl_up_sync(0xffffffffu, x, off);
        if (lane >= off) x += y;
    }
    __shared__ int ws[4];
    if (lane == 31) ws[wid] = x;
    __syncthreads();
    int woff = 0;
    for (int w = 0; w < wid; w++) woff += ws[w];
    if (t < NB) g_boff[mp][t] = woff + x - v;
}

__global__ void scan_final(int mp) {
    int t = threadIdx.x, lane = t & 31, wid = t >> 5;
    int i = blockIdx.x * 256 + t;
    int v = (i < NN) ? g_deg[mp][i] : 0;
    int x = v;
#pragma unroll
    for (int off = 1; off < 32; off <<= 1) {
        int y = __shfl_up_sync(0xffffffffu, x, off);
        if (lane >= off) x += y;
    }
    __shared__ int ws[8];
    if (lane == 31) ws[wid] = x;
    __syncthreads();
    int woff = 0;
    for (int w = 0; w < wid; w++) woff += ws[w];
    int excl = g_boff[mp][blockIdx.x] + woff + x - v;
    if (i < NN) {
        g_rowptr[mp][i] = excl;
        g_cur[mp][i]    = excl;
        if (i == NN - 1) g_rowptr[mp][NN] = excl + v;
    }
}

__global__ void scatter_kernel(const int* __restrict__ src,
                               const int* __restrict__ dst, int mp) {
    int e = blockIdx.x * blockDim.x + threadIdx.x;
    if (e < EE) {
        int d = dst[mp * EE + e];
        int pos = atomicAdd(&g_cur[mp][d], 1);
        g_csr_src[mp][pos] = src[mp * EE + e];
    }
}

// ---------------- edge softmax + aggregation (per metapath) -----------------
__global__ void agg_kernel(const float* __restrict__ bias, int mp) {
    const int v  = blockIdx.x;
    const int t  = threadIdx.x;  // 128

    __shared__ float ser[HH], sden[HH];
    __shared__ float sex[16][HH];
    __shared__ int   ssrc[16];

    const int start = g_rowptr[mp][v];
    const int deg   = g_rowptr[mp][v + 1] - start;

    if (t < HH) {
        ser[t]  = g_er[mp][v][t];
        sden[t] = 0.f;
    }
    __syncthreads();

    float acc0 = 0.f, acc1 = 0.f, acc2 = 0.f, acc3 = 0.f;
    const int d0  = t * 4;
    const int myh = t >> 4;

    for (int base = 0; base < deg; base += 16) {
        int cn = min(16, deg - base);
        if (t < cn * 8) {
            int i = t >> 3, hh = t & 7;
            int s = g_csr_src[mp][start + base + i];
            if (hh == 0) ssrc[i] = s;
            float e = g_el[mp][s][hh] + ser[hh];
            e = (e > 0.f) ? e : 0.2f * e;
            sex[i][hh] = __expf(e);
        }
        __syncthreads();
        if (t < 8) {
            float dsum = 0.f;
            for (int i = 0; i < cn; i++) dsum += sex[i][t];
            sden[t] += dsum;
        }
#pragma unroll 4
        for (int i = 0; i < cn; i++) {
            int s = ssrc[i];
            float w = sex[i][myh];
            uint2 raw = *(const uint2*)&g_feat_h[mp][s][d0];
            float2 f01 = __half22float2(*(__half2*)&raw.x);
            float2 f23 = __half22float2(*(__half2*)&raw.y);
            acc0 += w * f01.x;
            acc1 += w * f01.y;
            acc2 += w * f23.x;
            acc3 += w * f23.y;
        }
        __syncthreads();
    }

    float inv = 1.f / fmaxf(sden[myh], 1e-9f);
    const float* b = bias + mp * HD + d0;
    float o0 = acc0 * inv + b[0];
    float o1 = acc1 * inv + b[1];
    float o2 = acc2 * inv + b[2];
    float o3 = acc3 * inv + b[3];
    o0 = (o0 > 0.f) ? o0 : (__expf(o0) - 1.f);
    o1 = (o1 > 0.f) ? o1 : (__expf(o1) - 1.f);
    o2 = (o2 > 0.f) ? o2 : (__expf(o2) - 1.f);
    o3 = (o3 > 0.f) ? o3 : (__expf(o3) - 1.f);
    uint2 zout;
    *(__half2*)&zout.x = __floats2half2_rn(o0, o1);
    *(__half2*)&zout.y = __floats2half2_rn(o2, o3);
    *(uint2*)&g_z_h[mp][v][d0] = zout;
}

// ---------------- semantic attention: fp16 MMA, pipelined, fused wsum -------
constexpr int SEM_STAGE = 15360;
constexpr int SEM_SMEM_BYTES = 2 * SEM_STAGE + 1536;

__global__ void __launch_bounds__(256, 2)
sem_mma_kernel(const float* __restrict__ b1, const float* __restrict__ W2) {
    extern __shared__ char smem[];
    float* s_b1 = (float*)(smem + 2 * SEM_STAGE);
    float* s_w2 = s_b1 + 128;
    float* s_wr = s_w2 + 128;   // 64
    uint32_t smem_u32;
    SMEM_U32(smem_u32, smem);

    const int t = threadIdx.x, lane = t & 31, wid = t >> 5;
    const int wm = wid & 1, wn = wid >> 1;
    const int rowBase = blockIdx.x * 64;
    const __half* Zh = &g_z_h[0][0][0];   // [40000][512]

    if (t < 128) { s_b1[t] = b1[t]; s_w2[t] = W2[t]; }
    if (t < 64) s_wr[t] = 0.f;

    const int l_in  = lane & 7;
    const int l_t01 = (lane >> 3) & 1;
    const int l_t23 = lane >> 4;
    const uint32_t a_off0 = (uint32_t)(wm * 32 + l_in + l_t01 * 8) * 80 + l_t23 * 16;
    const uint32_t b_off0 = 5120u + (uint32_t)(wn * 32 + l_in + (lane >> 4) * 8) * 80
                          + ((lane >> 3) & 1) * 16;

    auto cp_stage = [&](int kc, int buf) {
        uint32_t base = smem_u32 + buf * SEM_STAGE;
        {
            int row = t >> 2, q = t & 3;
            CP_ASYNC16(base + (uint32_t)row * 80 + q * 16,
                       Zh + (rowBase + row) * HD + kc * 32 + q * 8);
        }
#pragma unroll
        for (int j = 0; j < 2; j++) {
            int idx = t + j * 256;
            int row = idx >> 2, q = idx & 3;
            CP_ASYNC16(base + 5120 + (uint32_t)row * 80 + q * 16,
                       &g_W1t_h[row][kc * 32 + q * 8]);
        }
    };

    float d[2][4][4] = {};

    cp_stage(0, 0);
    CP_COMMIT();

    for (int kc = 0; kc < 16; kc++) {
        const int cur = kc & 1;
        if (kc < 15) {
            cp_stage(kc + 1, cur ^ 1);
            CP_COMMIT();
            CP_WAIT(1);
        } else {
            CP_WAIT(0);
        }
        __syncthreads();

        const uint32_t bufb = smem_u32 + cur * SEM_STAGE;
#pragma unroll
        for (int ks = 0; ks < 2; ks++) {
            const uint32_t kb = (uint32_t)ks * 32;
            uint32_t ah[2][4], bh[2][4];
#pragma unroll
            for (int mi = 0; mi < 2; mi++)
                LDSM_X4(ah[mi], bufb + a_off0 + (uint32_t)(mi * 16) * 80 + kb);
#pragma unroll
            for (int p = 0; p < 2; p++)
                LDSM_X4(bh[p], bufb + b_off0 + (uint32_t)(p * 16) * 80 + kb);
#pragma unroll
            for (int mi = 0; mi < 2; mi++)
#pragma unroll
                for (int p = 0; p < 2; p++)
#pragma unroll
                    for (int q = 0; q < 2; q++) {
                        int ni = p * 2 + q;
                        uint32_t bq[2] = { bh[p][q * 2], bh[p][q * 2 + 1] };
                        MMA_F16(d[mi][ni], ah[mi], bq);
                    }
        }
        __syncthreads();
    }

#pragma unroll
    for (int mi = 0; mi < 2; mi++) {
#pragma unroll
        for (int half = 0; half < 2; half++) {
            float p = 0.f;
#pragma unroll
            for (int ni = 0; ni < 4; ni++) {
                int c = wn * 32 + ni * 8 + (lane & 3) * 2;
                p += fast_tanh(d[mi][ni][half * 2 + 0] + s_b1[c]) * s_w2[c];
                p += fast_tanh(d[mi][ni][half * 2 + 1] + s_b1[c + 1]) * s_w2[c + 1];
            }
            p += __shfl_xor_sync(0xffffffffu, p, 1);
            p += __shfl_xor_sync(0xffffffffu, p, 2);
            if ((lane & 3) == 0)
                atomicAdd(&s_wr[wm * 32 + mi * 16 + half * 8 + (lane >> 2)], p);
        }
    }
    __syncthreads();
    if (t < 64) {
        float v = s_wr[t];
        int grow = rowBase + t;
        float v0 = (grow < NN) ? v : 0.f;
        float v1 = (grow >= NN) ? v : 0.f;
#pragma unroll
        for (int off = 16; off; off >>= 1) {
            v0 += __shfl_xor_sync(0xffffffffu, v0, off);
            v1 += __shfl_xor_sync(0xffffffffu, v1, off);
        }
        if (lane == 0) {
            atomicAdd(&g_wsum[0], v0);
            atomicAdd(&g_wsum[1], v1);
        }
    }
}

__global__ void beta_kernel() {
    float a = g_wsum[0] / (float)NN;
    float b = g_wsum[1] / (float)NN;
    float m = fmaxf(a, b);
    float ea = __expf(a - m), eb = __expf(b - m);
    float s = ea + eb;
    g_beta[0] = ea / s;
    g_beta[1] = eb / s;
}

// ---------------- prediction via fp16 MMA -----------------------------------
constexpr int PRED_SMEM_BYTES = 256 * 80;

__global__ void __launch_bounds__(256)
pred_mma_kernel(const float* __restrict__ pw, const float* __restrict__ pb,
                float* __restrict__ out) {
    extern __shared__ char smem[];
    uint32_t smem_u32;
    SMEM_U32(smem_u32, smem);

    const int t = threadIdx.x, lane = t & 31, wid = t >> 5;
    const int rowBase = blockIdx.x * 256;
    const float b0 = g_beta[0], b1 = g_beta[1];

    const int l_in  = lane & 7;
    const int l_t01 = (lane >> 3) & 1;
    const int l_t23 = lane >> 4;
    const uint32_t a_off0 = (uint32_t)(wid * 32 + l_in + l_t01 * 8) * 80 + l_t23 * 16;

    const int n_col = lane >> 2;
    const bool nval = n_col < CC;

    float d[2][4] = {};

    for (int kc = 0; kc < 16; kc++) {
        {
            int grow = rowBase + t;
            uint4 o[4];
            if (grow < NN) {
                const uint4* z0p = (const uint4*)&g_z_h[0][grow][kc * 32];
                const uint4* z1p = (const uint4*)&g_z_h[1][grow][kc * 32];
#pragma unroll
                for (int w = 0; w < 4; w++) {
                    uint4 za = z0p[w], zb = z1p[w];
                    o[w].x = comb2(za.x, zb.x, b0, b1);
                    o[w].y = comb2(za.y, zb.y, b0, b1);
                    o[w].z = comb2(za.z, zb.z, b0, b1);
                    o[w].w = comb2(za.w, zb.w, b0, b1);
                }
            } else {
#pragma unroll
                for (int w = 0; w < 4; w++) o[w] = make_uint4(0, 0, 0, 0);
            }
            char* dstp = smem + t * 80;
#pragma unroll
            for (int w = 0; w < 4; w++) *(uint4*)(dstp + w * 16) = o[w];
        }
        __syncthreads();

#pragma unroll
        for (int ks = 0; ks < 2; ks++) {
            uint32_t a0[4], a1[4];
            LDSM_X4(a0, smem_u32 + a_off0 + (uint32_t)ks * 32);
            LDSM_X4(a1, smem_u32 + a_off0 + 16u * 80 + (uint32_t)ks * 32);
            int kk = kc * 32 + ks * 16 + (lane & 3) * 2;
            uint32_t br[2] = {0, 0};
            if (nval) {
                __half2 q0 = __floats2half2_rn(pw[kk * CC + n_col], pw[(kk + 1) * CC + n_col]);
                __half2 q1 = __floats2half2_rn(pw[(kk + 8) * CC + n_col], pw[(kk + 9) * CC + n_col]);
                br[0] = *(uint32_t*)&q0;
                br[1] = *(uint32_t*)&q1;
            }
            MMA_F16(d[0], a0, br);
            MMA_F16(d[1], a1, br);
        }
        __syncthreads();
    }

#pragma unroll
    for (int mi = 0; mi < 2; mi++) {
#pragma unroll
        for (int half = 0; half < 2; half++) {
            int grow = rowBase + wid * 32 + mi * 16 + half * 8 + (lane >> 2);
            int c0 = (lane & 3) * 2;
            if (grow < NN) {
                if (c0 < CC)     out[grow * CC + c0]     = d[mi][half * 2 + 0] + pb[c0];
                if (c0 + 1 < CC) out[grow * CC + c0 + 1] = d[mi][half * 2 + 1] + pb[c0 + 1];
            }
        }
    }
}

// ---------------- launch ----------------
extern "C" void kernel_launch(void* const* d_in, const int* in_sizes, int n_in,
                              void* d_out, int out_size) {
    const float* h      = (const float*)d_in[0];
    const int*   src    = (const int*)d_in[1];
    const int*   dst    = (const int*)d_in[2];
    const float* W      = (const float*)d_in[3];
    const float* attn_l = (const float*)d_in[4];
    const float* attn_r = (const float*)d_in[5];
    const float* bias_g = (const float*)d_in[6];
    const float* sem_W1 = (const float*)d_in[7];
    const float* sem_b1 = (const float*)d_in[8];
    const float* sem_W2 = (const float*)d_in[9];
    const float* pred_W = (const float*)d_in[10];
    const float* pred_b = (const float*)d_in[11];
    float* out = (float*)d_out;

    static cudaStream_t s2 = nullptr, s3 = nullptr;
    static cudaEvent_t ev_fork = nullptr, ev_csr0 = nullptr, ev_csr1 = nullptr;
    static cudaEvent_t ev_f0 = nullptr, ev_a0 = nullptr;
    if (s2 == nullptr) {
        cudaStreamCreateWithFlags(&s2, cudaStreamNonBlocking);
        cudaStreamCreateWithFlags(&s3, cudaStreamNonBlocking);
        cudaEventCreateWithFlags(&ev_fork, cudaEventDisableTiming);
        cudaEventCreateWithFlags(&ev_csr0, cudaEventDisableTiming);
        cudaEventCreateWithFlags(&ev_csr1, cudaEventDisableTiming);
        cudaEventCreateWithFlags(&ev_f0, cudaEventDisableTiming);
        cudaEventCreateWithFlags(&ev_a0, cudaEventDisableTiming);
    }

    cudaFuncSetAttribute(feat_mma_kernel,
                         cudaFuncAttributeMaxDynamicSharedMemorySize, FEAT_SMEM_BYTES);
    cudaFuncSetAttribute(sem_mma_kernel,
                         cudaFuncAttributeMaxDynamicSharedMemorySize, SEM_SMEM_BYTES);
    cudaFuncSetAttribute(pred_mma_kernel,
                         cudaFuncAttributeMaxDynamicSharedMemorySize, PRED_SMEM_BYTES);

    void* p_deg = nullptr;
    void* p_ws  = nullptr;
    cudaGetSymbolAddress(&p_deg, g_deg);
    cudaGetSymbolAddress(&p_ws, g_wsum);
    cudaMemsetAsync(p_deg, 0, sizeof(int) * MM * NN, 0);        // launch 1
    cudaMemsetAsync(p_ws, 0, sizeof(float) * MM, 0);            // launch 2

    cudaEventRecord(ev_fork, 0);
    cudaStreamWaitEvent(s2, ev_fork, 0);

    count_kernel<<<(EE + 255) / 256, 256, 0, s2>>>(dst, 0);     // launch 3
    conv_h_kernel<<<(NPAD * FF / 8 + 255) / 256, 256>>>(h);     // launch 4
    {
        dim3 grid(HD / 32, FF / 32, MM);
        conv_w_kernel<<<grid, dim3(32, 8)>>>(W);                // launch 5
    }
    {
        dim3 grid((NN + 127) / 128, HD / 128);
        feat_mma_kernel<<<grid, 256, FEAT_SMEM_BYTES>>>(attn_l, attn_r, 0);  // launch 6
    }
    cudaEventRecord(ev_f0, 0);

    // CSR mp0 remainder on s2
    scan_partial<<<NB, 256, 0, s2>>>(0);
    scan_mid<<<1, 128, 0, s2>>>(0);
    scan_final<<<NB, 256, 0, s2>>>(0);
    scatter_kernel<<<(EE + 255) / 256, 256, 0, s2>>>(src, dst, 0);
    cudaEventRecord(ev_csr0, s2);

    // agg mp0 on s3 (concurrent with feat mp1)
    cudaStreamWaitEvent(s3, ev_f0, 0);
    cudaStreamWaitEvent(s3, ev_csr0, 0);
    agg_kernel<<<NN, 128, 0, s3>>>(bias_g, 0);
    cudaEventRecord(ev_a0, s3);

    // feat mp1 on s0
    {
        dim3 grid((NN + 127) / 128, HD / 128);
        feat_mma_kernel<<<grid, 256, FEAT_SMEM_BYTES>>>(attn_l, attn_r, 1);
    }
    conv_w1t_kernel<<<dim3(HIDN / 32, HD / 32), dim3(32, 8)>>>(sem_W1);

    // CSR mp1 on s2
    count_kernel<<<(EE + 255) / 256, 256, 0, s2>>>(dst, 1);
    scan_partial<<<NB, 256, 0, s2>>>(1);
    scan_mid<<<1, 128, 0, s2>>>(1);
    scan_final<<<NB, 256, 0, s2>>>(1);
    scatter_kernel<<<(EE + 255) / 256, 256, 0, s2>>>(src, dst, 1);
    cudaEventRecord(ev_csr1, s2);

    // agg mp1 on s0
    cudaStreamWaitEvent(0, ev_csr1, 0);
    agg_kernel<<<NN, 128>>>(bias_g, 1);

    // join agg0, then sem/beta/pred
    cudaStreamWaitEvent(0, ev_a0, 0);
    sem_mma_kernel<<<(MM * NN) / 64, 256, SEM_SMEM_BYTES>>>(sem_b1, sem_W2);
    beta_kernel<<<1, 1>>>();
    pred_mma_kernel<<<(NN + 255) / 256, 256, PRED_SMEM_BYTES>>>(pred_W, pred_b, out);
}